// round 15
// baseline (speedup 1.0000x reference)
#include <cuda_runtime.h>
#include <math.h>
#include <stdint.h>

#define N_NODES 20000
#define NE      320000
#define ET      (NE + N_NODES)
#define HEADS   4

// ---------------- scratch (device globals; no allocation) ----------------
static __device__ float  g_xw0[(size_t)N_NODES * 256];
static __device__ float  g_h0 [(size_t)N_NODES * 256];
static __device__ float  g_xw1[(size_t)N_NODES * 128];
static __device__ float  g_h1 [(size_t)N_NODES * 128];
static __device__ float  g_z0 [(size_t)N_NODES * 128];
static __device__ float  g_z1 [(size_t)N_NODES * 64];
static __device__ float2 g_s0 [N_NODES * 4];    // two slots per (node, head)
static __device__ float2 g_d0 [N_NODES * 4];
static __device__ float2 g_s1 [N_NODES * 4];
static __device__ float2 g_d1 [N_NODES * 4];
static __device__ int    g_cnt[N_NODES];        // BSS-zero initially; scan re-zeros per replay
static __device__ int    g_cur[N_NODES];
static __device__ int    g_off[N_NODES + 1];
static __device__ int    g_csr[ET];
static __device__ float  g_wf01[256 * 256];     // [gatW1 ; fcW0]
static __device__ float  g_wkl0[256 * 128];     // [shW0 ; scW0]
static __device__ float  g_wkl1[128 * 64];      // [shW1 ; scW1]

// ---------------- helpers ----------------
__device__ __forceinline__ float softplusf(float x) {
    return x > 20.f ? x : log1pf(__expf(x));
}
__device__ __forceinline__ void edge_uv(const int* __restrict__ ei, int e, int& u, int& v) {
    if (e < NE) { u = ei[e]; v = ei[NE + e]; }
    else        { u = v = e - NE; }   // self loops appended
}
__device__ __forceinline__ float tf32_round(float x) {
    uint32_t u;
    asm("cvt.rna.tf32.f32 %0, %1;" : "=r"(u) : "f"(x));
    return __uint_as_float(u);
}
__device__ __forceinline__ void mma8(float* c, const float* a, const float* b) {
    asm volatile(
        "mma.sync.aligned.m16n8k8.row.col.f32.tf32.tf32.f32 "
        "{%0,%1,%2,%3}, {%4,%5,%6,%7}, {%8,%9}, {%0,%1,%2,%3};"
        : "+f"(c[0]), "+f"(c[1]), "+f"(c[2]), "+f"(c[3])
        : "r"(__float_as_uint(a[0])), "r"(__float_as_uint(a[1])),
          "r"(__float_as_uint(a[2])), "r"(__float_as_uint(a[3])),
          "r"(__float_as_uint(b[0])), "r"(__float_as_uint(b[1])));
}
__device__ __forceinline__ float slot2(const float2* __restrict__ buf, int idx) {
    float2 t = buf[idx];
    return t.x + t.y;
}

// ---------------- tiny fork kernel (capture-stream anchor for s2 fork) ----------------
__global__ void fork_kernel() {}

// ---------------- fused weight concat (one launch) ----------------
__global__ void concat_kernel(float* __restrict__ wf01, float* __restrict__ wkl0,
                              float* __restrict__ wkl1,
                              const float* __restrict__ gatW1, const float* __restrict__ fcW0,
                              const float* __restrict__ shW0, const float* __restrict__ scW0,
                              const float* __restrict__ shW1, const float* __restrict__ scW1) {
    int i = blockIdx.x * blockDim.x + threadIdx.x;
    if (i < 32768) { wf01[i] = gatW1[i]; wf01[32768 + i] = fcW0[i]; }
    if (i < 16384) { wkl0[i] = shW0[i]; wkl0[16384 + i] = scW0[i]; }
    if (i < 4096)  { wkl1[i] = shW1[i]; wkl1[4096 + i] = scW1[i]; }
}

// ================= CSR build (group edges by dst) =================
__global__ void hist_kernel(const int* __restrict__ ei, int* __restrict__ cnt) {
    int e = blockIdx.x * blockDim.x + threadIdx.x;
    if (e >= ET) return;
    int u, v; edge_uv(ei, e, u, v);
    (void)u;
    atomicAdd(&cnt[v], 1);
}

// single-block exclusive scan of cnt -> off; zero cur AND cnt (for next graph replay)
__global__ void scan_kernel(int* __restrict__ cnt, int* __restrict__ off,
                            int* __restrict__ cur) {
    const int CHUNK = (N_NODES + 1023) / 1024;   // 20
    __shared__ int ts[1024];
    int tid = threadIdx.x;
    int base = tid * CHUNK;
    int s = 0;
    for (int i = 0; i < CHUNK; i++) {
        int idx = base + i;
        if (idx < N_NODES) s += cnt[idx];
    }
    ts[tid] = s;
    __syncthreads();
    for (int o = 1; o < 1024; o <<= 1) {
        int v = (tid >= o) ? ts[tid - o] : 0;
        __syncthreads();
        ts[tid] += v;
        __syncthreads();
    }
    int run = (tid > 0) ? ts[tid - 1] : 0;
    for (int i = 0; i < CHUNK; i++) {
        int idx = base + i;
        if (idx < N_NODES) {
            off[idx] = run;
            run += cnt[idx];
            cnt[idx] = 0;
            cur[idx] = 0;
        }
    }
    if (tid == (N_NODES - 1) / CHUNK) off[N_NODES] = run;
}

__global__ void scatter_kernel(const int* __restrict__ ei, const int* __restrict__ off,
                               int* __restrict__ cur, int* __restrict__ csr) {
    int e = blockIdx.x * blockDim.x + threadIdx.x;
    if (e >= ET) return;
    int u, v; edge_uv(ei, e, u, v);
    int pos = off[v] + atomicAdd(&cur[v], 1);
    csr[pos] = u;
}

// ================= 3xTF32 mma.sync GEMM (BK=32, raw f32 smem, register split) ======
// mode: 0 plain rowmajor, 1 softplus rowmajor, 2 softplus+clip transposed,
//       3 softplus transposed, 4 plain rowmajor + GAT s/d slot stores (no atomics).
__global__ void __launch_bounds__(256, 2)
gemm_mma_kernel(const float* __restrict__ A, const float* __restrict__ W,
                int n, int K, int nsplit,
                float* __restrict__ outA, const float* __restrict__ biasA, int modeA, int strideA,
                float* __restrict__ outB, const float* __restrict__ biasB, int modeB, int strideB,
                const float* __restrict__ asrcP, const float* __restrict__ adstP,
                float2* __restrict__ sOut, float2* __restrict__ dOut, int headC) {
    constexpr int BM = 128, BN = 64, BK = 32;
    constexpr int KP = 36;
    constexpr int NT = 4;
    constexpr int AF4 = BM * BK / 4 / 256;     // 4
    constexpr int BF4 = BN * BK / 4 / 256;     // 2

    __shared__ __align__(16) float As[BM * KP];
    __shared__ __align__(16) float Bs[BN * KP];

    const int tid = threadIdx.x;
    const int wid = tid >> 5, lane = tid & 31;
    const int gr = lane >> 2, tig = lane & 3;
    const int warpM = (wid & 3) * 32;
    const int warpN = (wid >> 2) * 32;
    const int bi = blockIdx.x * BM;
    const int bj = blockIdx.y * BN;

    float acc[2][NT][4];
#pragma unroll
    for (int mt = 0; mt < 2; mt++)
#pragma unroll
        for (int nt = 0; nt < NT; nt++)
#pragma unroll
            for (int q = 0; q < 4; q++) acc[mt][nt][q] = 0.f;

    const int nchunk = K / BK;

    int arows[AF4], aqs[AF4]; bool avs[AF4];
#pragma unroll
    for (int i = 0; i < AF4; i++) {
        int idx = tid + i * 256;
        arows[i] = idx >> 3; aqs[i] = idx & 7;
        avs[i] = (bi + arows[i]) < n;
    }
    int brows[BF4], bqs[BF4];
#pragma unroll
    for (int i = 0; i < BF4; i++) {
        int idx = tid + i * 256;
        brows[i] = idx >> 3; bqs[i] = idx & 7;
    }

    float4 apre[AF4], bpre[BF4];
#pragma unroll
    for (int i = 0; i < AF4; i++)
        apre[i] = avs[i] ? *(const float4*)(A + (size_t)(bi + arows[i]) * K + aqs[i] * 4)
                         : make_float4(0.f, 0.f, 0.f, 0.f);
#pragma unroll
    for (int i = 0; i < BF4; i++)
        bpre[i] = *(const float4*)(W + (size_t)(bj + brows[i]) * K + bqs[i] * 4);

    for (int c = 0; c < nchunk; c++) {
#pragma unroll
        for (int i = 0; i < AF4; i++)
            *(float4*)&As[arows[i] * KP + aqs[i] * 4] = apre[i];
#pragma unroll
        for (int i = 0; i < BF4; i++)
            *(float4*)&Bs[brows[i] * KP + bqs[i] * 4] = bpre[i];
        __syncthreads();

        if (c + 1 < nchunk) {
            int k0 = (c + 1) * BK;
#pragma unroll
            for (int i = 0; i < AF4; i++)
                apre[i] = avs[i] ? *(const float4*)(A + (size_t)(bi + arows[i]) * K + k0 + aqs[i] * 4)
                                 : make_float4(0.f, 0.f, 0.f, 0.f);
#pragma unroll
            for (int i = 0; i < BF4; i++)
                bpre[i] = *(const float4*)(W + (size_t)(bj + brows[i]) * K + k0 + bqs[i] * 4);
        }

#pragma unroll
        for (int kb = 0; kb < BK; kb += 8) {
            float ah[2][4], al[2][4];
#pragma unroll
            for (int mt = 0; mt < 2; mt++) {
                int r0 = (warpM + mt * 16 + gr) * KP + kb + tig;
                int r1 = r0 + 8 * KP;
                float raw0 = As[r0], raw1 = As[r1], raw2 = As[r0 + 4], raw3 = As[r1 + 4];
                ah[mt][0] = tf32_round(raw0); al[mt][0] = raw0 - ah[mt][0];
                ah[mt][1] = tf32_round(raw1); al[mt][1] = raw1 - ah[mt][1];
                ah[mt][2] = tf32_round(raw2); al[mt][2] = raw2 - ah[mt][2];
                ah[mt][3] = tf32_round(raw3); al[mt][3] = raw3 - ah[mt][3];
            }
#pragma unroll
            for (int nt = 0; nt < NT; nt++) {
                int b0 = (warpN + nt * 8 + gr) * KP + kb + tig;
                float braw0 = Bs[b0], braw1 = Bs[b0 + 4];
                float bh[2], bl[2];
                bh[0] = tf32_round(braw0); bl[0] = braw0 - bh[0];
                bh[1] = tf32_round(braw1); bl[1] = braw1 - bh[1];
#pragma unroll
                for (int mt = 0; mt < 2; mt++) {
                    mma8(acc[mt][nt], ah[mt], bh);
                    mma8(acc[mt][nt], ah[mt], bl);
                    mma8(acc[mt][nt], al[mt], bh);
                }
            }
        }
        __syncthreads();
    }

    // ---- epilogue (segment uniform per warp: nsplit is a multiple of 32) ----
    const int jbase = bj + warpN;
    float* o; const float* bp; int mode, stride, joff;
    if (jbase < nsplit) { o = outA; bp = biasA; mode = modeA; stride = strideA; joff = 0; }
    else                { o = outB; bp = biasB; mode = modeB; stride = strideB; joff = nsplit; }

#pragma unroll
    for (int mt = 0; mt < 2; mt++) {
#pragma unroll
        for (int half = 0; half < 2; half++) {
            const int row = bi + warpM + mt * 16 + gr + half * 8;
            const bool rv = row < n;
            float ss = 0.f, dd = 0.f;
#pragma unroll
            for (int nt = 0; nt < NT; nt++) {
#pragma unroll
                for (int p = 0; p < 2; p++) {
                    int jj = jbase + nt * 8 + 2 * tig + p;
                    float v = acc[mt][nt][half * 2 + p];
                    int j = jj - joff;
                    if (mode == 4) {
                        if (rv) o[(size_t)row * stride + j] = v;
                        ss += v * asrcP[jj];
                        dd += v * adstP[jj];
                    } else if (rv) {
                        v += bp ? bp[j] : 0.f;
                        if (mode != 0) v = softplusf(v);
                        if (mode == 2) v = fminf(fmaxf(v, 0.1f), 1000.f);
                        if (mode >= 2) o[(size_t)j * stride + row] = v;
                        else           o[(size_t)row * stride + j] = v;
                    }
                }
            }
            if (mode == 4) {
                // reduce the 4 tig partials (8 cols each) to the full 32-col sums
                ss += __shfl_xor_sync(0xffffffffu, ss, 1);
                ss += __shfl_xor_sync(0xffffffffu, ss, 2);
                dd += __shfl_xor_sync(0xffffffffu, dd, 1);
                dd += __shfl_xor_sync(0xffffffffu, dd, 2);
                if (rv && tig == 0) {
                    int h = jbase / headC;
                    float* sp = (float*)&sOut[row * 4 + h];
                    float* dp = (float*)&dOut[row * 4 + h];
                    if (headC == 64) {             // two writer warps per (row,h)
                        int slot = (jbase >> 5) & 1;
                        sp[slot] = ss; dp[slot] = dd;
                    } else {                       // single writer warp
                        sp[0] = ss; sp[1] = 0.f;
                        dp[0] = dd; dp[1] = 0.f;
                    }
                }
            }
        }
    }
}

// ================= fused per-node GAT v3: single gather sweep =================
// Cache (u, e) for all (edge, head) in smem in ONE sweep (deg <= 64 nearly always:
// Poisson(16)+self-loop); warp-parallel per-head max/sum; normalize; aggregate.
// Fallback to 3-sweep path if deg > 64.
template <int C>
__global__ void gat_kernel(const int* __restrict__ csr, const int* __restrict__ off,
                           const float2* __restrict__ sS, const float2* __restrict__ dS,
                           const float* __restrict__ xw, const float* __restrict__ bias,
                           float* __restrict__ out) {
    constexpr int HC = 4 * C;
    constexpr int HQ = HC / 4;           // edge slots covered per sweep iteration
    constexpr int EMAX = 64;
    const int v = blockIdx.x;
    const int tid = threadIdx.x;
    const int wid = tid >> 5, lane = tid & 31;
    const int h = tid / C;
    const int hh = tid & 3;
    const int beg = off[v], end = off[v + 1];
    const int deg = end - beg;

    __shared__ float mh[4], inv[4];
    __shared__ float wsh[EMAX * 4];
    __shared__ int   ush[EMAX];

    if (deg <= EMAX) {
        // ---- single gather sweep: e for all (edge, head) ----
        const float dvh = slot2(dS, v * 4 + hh);
        for (int je = tid >> 2; je < deg; je += HQ) {
            int u = csr[beg + je];
            if (hh == 0) ush[je] = u;
            float e = slot2(sS, u * 4 + hh) + dvh;
            e = e > 0.f ? e : 0.2f * e;
            wsh[je * 4 + hh] = e;
        }
        __syncthreads();

        // ---- per-head max + expsum (warp w handles head w) ----
        if (wid < 4) {
            float m = -INFINITY;
            for (int q = lane; q < deg; q += 32) m = fmaxf(m, wsh[q * 4 + wid]);
#pragma unroll
            for (int o = 16; o; o >>= 1) m = fmaxf(m, __shfl_xor_sync(0xffffffffu, m, o));
            float sm = 0.f;
            for (int q = lane; q < deg; q += 32) sm += __expf(wsh[q * 4 + wid] - m);
#pragma unroll
            for (int o = 16; o; o >>= 1) sm += __shfl_xor_sync(0xffffffffu, sm, o);
            if (lane == 0) { mh[wid] = m; inv[wid] = 1.f / (sm + 1e-16f); }
        }
        __syncthreads();

        // ---- normalize weights in smem ----
        for (int je = tid >> 2; je < deg; je += HQ)
            wsh[je * 4 + hh] = __expf(wsh[je * 4 + hh] - mh[hh]) * inv[hh];
        __syncthreads();

        // ---- aggregate ----
        float acc = 0.f;
#pragma unroll 4
        for (int q = 0; q < deg; q++)
            acc = fmaf(wsh[q * 4 + h], xw[(size_t)ush[q] * HC + tid], acc);
        out[(size_t)v * HC + tid] = acc + bias[tid];
        return;
    }

    // ---------- fallback (deg > EMAX): 3-sweep path ----------
    __shared__ float red[HC];
    const int c = tid - h * C;
    const float dv = slot2(dS, v * 4 + h);

    float lmax = -INFINITY;
    for (int j = beg + c; j < end; j += C) {
        int u = csr[j];
        float e = slot2(sS, u * 4 + h) + dv;
        e = e > 0.f ? e : 0.2f * e;
        lmax = fmaxf(lmax, e);
    }
    red[tid] = lmax;
    __syncthreads();
    if (tid < 4) {
        float m = -INFINITY;
        for (int i = 0; i < C; i++) m = fmaxf(m, red[tid * C + i]);
        mh[tid] = m;
    }
    __syncthreads();
    const float m = mh[h];

    float lsum = 0.f;
    for (int j = beg + c; j < end; j += C) {
        int u = csr[j];
        float e = slot2(sS, u * 4 + h) + dv;
        e = e > 0.f ? e : 0.2f * e;
        lsum += __expf(e - m);
    }
    red[tid] = lsum;
    __syncthreads();
    if (tid < 4) {
        float sm = 0.f;
        for (int i = 0; i < C; i++) sm += red[tid * C + i];
        inv[tid] = 1.f / (sm + 1e-16f);
    }
    __syncthreads();
    const float invden = inv[h];

    float acc = 0.f;
    for (int j = beg; j < end; j++) {
        int u = csr[j];
        float e = slot2(sS, u * 4 + h) + dv;
        e = e > 0.f ? e : 0.2f * e;
        float w = __expf(e - m) * invden;
        acc = fmaf(w, xw[(size_t)u * HC + tid], acc);
    }
    out[(size_t)v * HC + tid] = acc + bias[tid];
}

// ---------------- fused kl_fix + theta ----------------
__global__ void theta_kernel(const float* __restrict__ k, float* __restrict__ l,
                             const float* __restrict__ eps, float* __restrict__ th, int ZN) {
    int i = blockIdx.x * blockDim.x + threadIdx.x;
    if (i >= ZN) return;
    float kk = k[i];
    float invk = 1.f / kk;
    float ll = fmaxf(l[i], 2.2e-10f) * expf(-lgammaf(1.f + invk));
    l[i] = ll;
    float acc = 0.f;
#pragma unroll
    for (int s = 0; s < 10; s++) {
        float ep = eps[(size_t)s * ZN + i];
        float t = fmaxf(1.f - ep, 2.2e-10f);
        float nl = -__logf(t);
        acc += __powf(nl, invk);
    }
    float theta = ll * acc * 0.1f;
    th[i] = fminf(fmaxf(theta, 2.2e-10f), 1000.f);
}

// ---------------- host launch ----------------
template <typename T>
static float* symaddrf(T& sym) { void* p = nullptr; cudaGetSymbolAddress(&p, sym); return (float*)p; }
template <typename T>
static float2* symaddrf2(T& sym) { void* p = nullptr; cudaGetSymbolAddress(&p, sym); return (float2*)p; }
template <typename T>
static int* symaddri(T& sym) { void* p = nullptr; cudaGetSymbolAddress(&p, sym); return (int*)p; }

static cudaStream_t g_s2 = nullptr;
static cudaEvent_t g_evFork, g_evCSR, g_evZ0, g_evT0;

extern "C" void kernel_launch(void* const* d_in, const int* in_sizes, int n_in,
                              void* d_out, int out_size) {
    if (!g_s2) {
        cudaStreamCreateWithFlags(&g_s2, cudaStreamNonBlocking);
        cudaEventCreateWithFlags(&g_evFork, cudaEventDisableTiming);
        cudaEventCreateWithFlags(&g_evCSR,  cudaEventDisableTiming);
        cudaEventCreateWithFlags(&g_evZ0,   cudaEventDisableTiming);
        cudaEventCreateWithFlags(&g_evT0,   cudaEventDisableTiming);
    }

    const float* x     = (const float*)d_in[0];
    const int*   ei    = (const int*)  d_in[1];
    const float* gatW0 = (const float*)d_in[2];
    const float* asrc0 = (const float*)d_in[3];
    const float* adst0 = (const float*)d_in[4];
    const float* gatb0 = (const float*)d_in[5];
    const float* fcW0  = (const float*)d_in[6];
    const float* fcb0  = (const float*)d_in[7];
    const float* shW0  = (const float*)d_in[8];
    const float* shb0  = (const float*)d_in[9];
    const float* scW0  = (const float*)d_in[10];
    const float* scb0  = (const float*)d_in[11];
    const float* gatW1 = (const float*)d_in[12];
    const float* asrc1 = (const float*)d_in[13];
    const float* adst1 = (const float*)d_in[14];
    const float* gatb1 = (const float*)d_in[15];
    const float* fcW1  = (const float*)d_in[16];
    const float* fcb1  = (const float*)d_in[17];
    const float* shW1  = (const float*)d_in[18];
    const float* shb1  = (const float*)d_in[19];
    const float* scW1  = (const float*)d_in[20];
    const float* scb1  = (const float*)d_in[21];
    const float* eps0  = (const float*)d_in[22];
    const float* eps1  = (const float*)d_in[23];

    const int n = N_NODES;
    float* out = (float*)d_out;
    float* theta0 = out;
    float* theta1 = theta0 + (size_t)128 * n;
    float* k0     = theta1 + (size_t)64  * n;
    float* k1     = k0     + (size_t)128 * n;
    float* l0     = k1     + (size_t)64  * n;
    float* l1     = l0     + (size_t)128 * n;

    float* xw0 = symaddrf(g_xw0);
    float* h0  = symaddrf(g_h0);
    float* xw1 = symaddrf(g_xw1);
    float* h1  = symaddrf(g_h1);
    float* z0  = symaddrf(g_z0);
    float* z1  = symaddrf(g_z1);
    float2* s0 = symaddrf2(g_s0);
    float2* d0 = symaddrf2(g_d0);
    float2* s1 = symaddrf2(g_s1);
    float2* d1 = symaddrf2(g_d1);
    float* wf01 = symaddrf(g_wf01);
    float* wkl0 = symaddrf(g_wkl0);
    float* wkl1 = symaddrf(g_wkl1);
    int* cnt = symaddri(g_cnt);
    int* cur = symaddri(g_cur);
    int* off = symaddri(g_off);
    int* csr = symaddri(g_csr);

    const int EB = (ET + 255) / 256;
    const int GX = (n + 127) / 128;       // 157 row tiles

    // ===== d: fork anchor (required so s2 joins the capture graph) =====
    fork_kernel<<<1, 1>>>();                                                          // 0
    cudaEventRecord(g_evFork, 0);
    cudaStreamWaitEvent(g_s2, g_evFork, 0);

    // ---- s2: CSR build + weight concat (overlaps xw0 GEMM on d) ----
    hist_kernel<<<EB, 256, 0, g_s2>>>(ei, cnt);                                       // 1
    scan_kernel<<<1, 1024, 0, g_s2>>>(cnt, off, cur);                                 // 2
    // ---- d: xw0 GEMM at capture index 3 (mode 4 -> xw0, s0, d0 slots) ----
    gemm_mma_kernel<<<dim3(GX, 4), 256>>>(x, gatW0, n, 256, 1 << 30,
                                          xw0, nullptr, 4, 256,
                                          nullptr, nullptr, 0, 0,
                                          asrc0, adst0, s0, d0, 64);                   // 3 (profiled)
    scatter_kernel<<<EB, 256, 0, g_s2>>>(ei, off, cur, csr);
    concat_kernel<<<128, 256, 0, g_s2>>>(wf01, wkl0, wkl1, gatW1, fcW0, shW0, scW0, shW1, scW1);
    cudaEventRecord(g_evCSR, g_s2);

    // ---- d: join CSR+concat, layer-0 GAT + fused xw1/z0 GEMM ----
    cudaStreamWaitEvent(0, g_evCSR, 0);
    gat_kernel<64><<<n, 256>>>(csr, off, s0, d0, xw0, gatb0, h0);
    gemm_mma_kernel<<<dim3(GX, 4), 256>>>(h0, wf01, n, 256, 128,
                                          xw1, nullptr, 4, 128,
                                          z0, fcb0, 1, 128,
                                          asrc1, adst1, s1, d1, 32);
    cudaEventRecord(g_evZ0, 0);

    // ---- s2: layer-0 head chain (kl0 -> theta0), overlaps with layer-1 chain on d ----
    cudaStreamWaitEvent(g_s2, g_evZ0, 0);
    gemm_mma_kernel<<<dim3(GX, 4), 256, 0, g_s2>>>(z0, wkl0, n, 128, 128,
                                                   k0, shb0, 2, n,
                                                   l0, scb0, 3, n,
                                                   nullptr, nullptr, nullptr, nullptr, 1);
    theta_kernel<<<(128 * n + 255) / 256, 256, 0, g_s2>>>(k0, l0, eps0, theta0, 128 * n);
    cudaEventRecord(g_evT0, g_s2);

    // ---- d: layer-1 chain (gat1 -> z1 -> kl1 -> theta1) ----
    gat_kernel<32><<<n, 128>>>(csr, off, s1, d1, xw1, gatb1, h1);
    gemm_mma_kernel<<<dim3(GX, 1), 256>>>(h1, fcW1, n, 128, 1 << 30,
                                          z1, fcb1, 1, 64,
                                          nullptr, nullptr, 0, 0,
                                          nullptr, nullptr, nullptr, nullptr, 1);
    gemm_mma_kernel<<<dim3(GX, 2), 256>>>(z1, wkl1, n, 64, 64,
                                          k1, shb1, 2, n,
                                          l1, scb1, 3, n,
                                          nullptr, nullptr, nullptr, nullptr, 1);
    theta_kernel<<<(64 * n + 255) / 256, 256>>>(k1, l1, eps1, theta1, 64 * n);

    // ---- join s2 back into d before return ----
    cudaStreamWaitEvent(0, g_evT0, 0);
}

// round 16
// speedup vs baseline: 1.0138x; 1.0138x over previous
#include <cuda_runtime.h>
#include <math.h>
#include <stdint.h>

#define N_NODES 20000
#define NE      320000
#define ET      (NE + N_NODES)
#define HEADS   4

// ---------------- scratch (device globals; no allocation) ----------------
static __device__ float g_xw0[(size_t)N_NODES * 256];
static __device__ float g_h0 [(size_t)N_NODES * 256];
static __device__ float g_xw1[(size_t)N_NODES * 128];
static __device__ float g_h1 [(size_t)N_NODES * 128];
static __device__ float g_z0 [(size_t)N_NODES * 128];
static __device__ float g_z1 [(size_t)N_NODES * 64];
static __device__ float g_s0 [N_NODES * 4];
static __device__ float g_d0 [N_NODES * 4];
static __device__ float g_s1 [N_NODES * 4];
static __device__ float g_d1 [N_NODES * 4];
static __device__ int   g_cnt[N_NODES];
static __device__ int   g_cur[N_NODES];
static __device__ int   g_off[N_NODES + 1];
static __device__ int   g_csr[ET];
static __device__ float g_wf01[256 * 256];   // [gatW1 ; fcW0]
static __device__ float g_wkl0[256 * 128];   // [shW0 ; scW0]
static __device__ float g_wkl1[128 * 64];    // [shW1 ; scW1]

// ---------------- helpers ----------------
__device__ __forceinline__ float softplusf(float x) {
    return x > 20.f ? x : log1pf(__expf(x));
}
__device__ __forceinline__ void edge_uv(const int* __restrict__ ei, int e, int& u, int& v) {
    if (e < NE) { u = ei[e]; v = ei[NE + e]; }
    else        { u = v = e - NE; }   // self loops appended
}
__device__ __forceinline__ float tf32_round(float x) {
    uint32_t u;
    asm("cvt.rna.tf32.f32 %0, %1;" : "=r"(u) : "f"(x));
    return __uint_as_float(u);
}
__device__ __forceinline__ void mma8(float* c, const float* a, const float* b) {
    asm volatile(
        "mma.sync.aligned.m16n8k8.row.col.f32.tf32.tf32.f32 "
        "{%0,%1,%2,%3}, {%4,%5,%6,%7}, {%8,%9}, {%0,%1,%2,%3};"
        : "+f"(c[0]), "+f"(c[1]), "+f"(c[2]), "+f"(c[3])
        : "r"(__float_as_uint(a[0])), "r"(__float_as_uint(a[1])),
          "r"(__float_as_uint(a[2])), "r"(__float_as_uint(a[3])),
          "r"(__float_as_uint(b[0])), "r"(__float_as_uint(b[1])));
}

// ---------------- fused init: zero cnt + all 4 s/d buffers ----------------
__global__ void init_kernel(int* __restrict__ cnt, float* __restrict__ s0,
                            float* __restrict__ d0, float* __restrict__ s1,
                            float* __restrict__ d1) {
    int i = blockIdx.x * blockDim.x + threadIdx.x;
    if (i < N_NODES) cnt[i] = 0;
    if (i < N_NODES * 4) { s0[i] = 0.f; d0[i] = 0.f; s1[i] = 0.f; d1[i] = 0.f; }
}

// ---------------- fused weight concat (one launch) ----------------
__global__ void concat_kernel(float* __restrict__ wf01, float* __restrict__ wkl0,
                              float* __restrict__ wkl1,
                              const float* __restrict__ gatW1, const float* __restrict__ fcW0,
                              const float* __restrict__ shW0, const float* __restrict__ scW0,
                              const float* __restrict__ shW1, const float* __restrict__ scW1) {
    int i = blockIdx.x * blockDim.x + threadIdx.x;
    if (i < 32768) { wf01[i] = gatW1[i]; wf01[32768 + i] = fcW0[i]; }
    if (i < 16384) { wkl0[i] = shW0[i]; wkl0[16384 + i] = scW0[i]; }
    if (i < 4096)  { wkl1[i] = shW1[i]; wkl1[4096 + i] = scW1[i]; }
}

// ================= CSR build (group edges by dst) =================
__global__ void hist_kernel(const int* __restrict__ ei, int* __restrict__ cnt) {
    int e = blockIdx.x * blockDim.x + threadIdx.x;
    if (e >= ET) return;
    int u, v; edge_uv(ei, e, u, v);
    (void)u;
    atomicAdd(&cnt[v], 1);
}

__global__ void scan_kernel(const int* __restrict__ cnt, int* __restrict__ off,
                            int* __restrict__ cur) {
    const int CHUNK = (N_NODES + 1023) / 1024;   // 20
    __shared__ int ts[1024];
    int tid = threadIdx.x;
    int base = tid * CHUNK;
    int s = 0;
    for (int i = 0; i < CHUNK; i++) {
        int idx = base + i;
        if (idx < N_NODES) s += cnt[idx];
    }
    ts[tid] = s;
    __syncthreads();
    for (int o = 1; o < 1024; o <<= 1) {
        int v = (tid >= o) ? ts[tid - o] : 0;
        __syncthreads();
        ts[tid] += v;
        __syncthreads();
    }
    int run = (tid > 0) ? ts[tid - 1] : 0;
    for (int i = 0; i < CHUNK; i++) {
        int idx = base + i;
        if (idx < N_NODES) {
            off[idx] = run;
            run += cnt[idx];
            cur[idx] = 0;
        }
    }
    if (tid == (N_NODES - 1) / CHUNK) off[N_NODES] = run;
}

__global__ void scatter_kernel(const int* __restrict__ ei, const int* __restrict__ off,
                               int* __restrict__ cur, int* __restrict__ csr) {
    int e = blockIdx.x * blockDim.x + threadIdx.x;
    if (e >= ET) return;
    int u, v; edge_uv(ei, e, u, v);
    int pos = off[v] + atomicAdd(&cur[v], 1);
    csr[pos] = u;
}

// ======= 3xTF32 mma.sync GEMM (BK=32, A register-split, B pre-split in smem) =======
// mode: 0 plain rowmajor, 1 softplus rowmajor, 2 softplus+clip transposed,
//       3 softplus transposed, 4 plain rowmajor + GAT s/d accumulation (atomicAdd).
__global__ void __launch_bounds__(256, 2)
gemm_mma_kernel(const float* __restrict__ A, const float* __restrict__ W,
                int n, int K, int nsplit,
                float* __restrict__ outA, const float* __restrict__ biasA, int modeA, int strideA,
                float* __restrict__ outB, const float* __restrict__ biasB, int modeB, int strideB,
                const float* __restrict__ asrcP, const float* __restrict__ adstP,
                float* __restrict__ sOut, float* __restrict__ dOut, int headC) {
    constexpr int BM = 128, BN = 64, BK = 32;
    constexpr int KP = 36;
    constexpr int NT = 4;
    constexpr int AF4 = BM * BK / 4 / 256;     // 4
    constexpr int BF4 = BN * BK / 4 / 256;     // 2

    __shared__ __align__(16) float As [BM * KP];
    __shared__ __align__(16) float Bsh[BN * KP];
    __shared__ __align__(16) float Bsl[BN * KP];

    const int tid = threadIdx.x;
    const int wid = tid >> 5, lane = tid & 31;
    const int gr = lane >> 2, tig = lane & 3;
    const int warpM = (wid & 3) * 32;
    const int warpN = (wid >> 2) * 32;
    const int bi = blockIdx.x * BM;
    const int bj = blockIdx.y * BN;

    float acc[2][NT][4];
#pragma unroll
    for (int mt = 0; mt < 2; mt++)
#pragma unroll
        for (int nt = 0; nt < NT; nt++)
#pragma unroll
            for (int q = 0; q < 4; q++) acc[mt][nt][q] = 0.f;

    const int nchunk = K / BK;

    int arows[AF4], aqs[AF4]; bool avs[AF4];
#pragma unroll
    for (int i = 0; i < AF4; i++) {
        int idx = tid + i * 256;
        arows[i] = idx >> 3; aqs[i] = idx & 7;
        avs[i] = (bi + arows[i]) < n;
    }
    int brows[BF4], bqs[BF4];
#pragma unroll
    for (int i = 0; i < BF4; i++) {
        int idx = tid + i * 256;
        brows[i] = idx >> 3; bqs[i] = idx & 7;
    }

    float4 apre[AF4], bpre[BF4];
#pragma unroll
    for (int i = 0; i < AF4; i++)
        apre[i] = avs[i] ? *(const float4*)(A + (size_t)(bi + arows[i]) * K + aqs[i] * 4)
                         : make_float4(0.f, 0.f, 0.f, 0.f);
#pragma unroll
    for (int i = 0; i < BF4; i++)
        bpre[i] = *(const float4*)(W + (size_t)(bj + brows[i]) * K + bqs[i] * 4);

    for (int c = 0; c < nchunk; c++) {
#pragma unroll
        for (int i = 0; i < AF4; i++)
            *(float4*)&As[arows[i] * KP + aqs[i] * 4] = apre[i];
#pragma unroll
        for (int i = 0; i < BF4; i++) {
            float4 v = bpre[i];
            float4 h, l;
            h.x = tf32_round(v.x); l.x = v.x - h.x;
            h.y = tf32_round(v.y); l.y = v.y - h.y;
            h.z = tf32_round(v.z); l.z = v.z - h.z;
            h.w = tf32_round(v.w); l.w = v.w - h.w;
            *(float4*)&Bsh[brows[i] * KP + bqs[i] * 4] = h;
            *(float4*)&Bsl[brows[i] * KP + bqs[i] * 4] = l;
        }
        __syncthreads();

        if (c + 1 < nchunk) {
            int k0 = (c + 1) * BK;
#pragma unroll
            for (int i = 0; i < AF4; i++)
                apre[i] = avs[i] ? *(const float4*)(A + (size_t)(bi + arows[i]) * K + k0 + aqs[i] * 4)
                                 : make_float4(0.f, 0.f, 0.f, 0.f);
#pragma unroll
            for (int i = 0; i < BF4; i++)
                bpre[i] = *(const float4*)(W + (size_t)(bj + brows[i]) * K + k0 + bqs[i] * 4);
        }

#pragma unroll
        for (int kb = 0; kb < BK; kb += 8) {
            float ah[2][4], al[2][4];
#pragma unroll
            for (int mt = 0; mt < 2; mt++) {
                int r0 = (warpM + mt * 16 + gr) * KP + kb + tig;
                int r1 = r0 + 8 * KP;
                float raw0 = As[r0], raw1 = As[r1], raw2 = As[r0 + 4], raw3 = As[r1 + 4];
                ah[mt][0] = tf32_round(raw0); al[mt][0] = raw0 - ah[mt][0];
                ah[mt][1] = tf32_round(raw1); al[mt][1] = raw1 - ah[mt][1];
                ah[mt][2] = tf32_round(raw2); al[mt][2] = raw2 - ah[mt][2];
                ah[mt][3] = tf32_round(raw3); al[mt][3] = raw3 - ah[mt][3];
            }
#pragma unroll
            for (int nt = 0; nt < NT; nt++) {
                int b0 = (warpN + nt * 8 + gr) * KP + kb + tig;
                float bh[2] = {Bsh[b0], Bsh[b0 + 4]};
                float bl[2] = {Bsl[b0], Bsl[b0 + 4]};
#pragma unroll
                for (int mt = 0; mt < 2; mt++) {
                    mma8(acc[mt][nt], ah[mt], bh);
                    mma8(acc[mt][nt], ah[mt], bl);
                    mma8(acc[mt][nt], al[mt], bh);
                }
            }
        }
        __syncthreads();
    }

    // ---- epilogue (segment uniform per warp: nsplit is a multiple of 32) ----
    const int jbase = bj + warpN;
    float* o; const float* bp; int mode, stride, joff;
    if (jbase < nsplit) { o = outA; bp = biasA; mode = modeA; stride = strideA; joff = 0; }
    else                { o = outB; bp = biasB; mode = modeB; stride = strideB; joff = nsplit; }

#pragma unroll
    for (int mt = 0; mt < 2; mt++) {
#pragma unroll
        for (int half = 0; half < 2; half++) {
            int row = bi + warpM + mt * 16 + gr + half * 8;
            if (row >= n) continue;
            float ss = 0.f, dd = 0.f;
#pragma unroll
            for (int nt = 0; nt < NT; nt++) {
#pragma unroll
                for (int p = 0; p < 2; p++) {
                    int jj = jbase + nt * 8 + 2 * tig + p;
                    float v = acc[mt][nt][half * 2 + p];
                    int j = jj - joff;
                    if (mode == 4) {
                        o[(size_t)row * stride + j] = v;
                        ss += v * asrcP[jj];
                        dd += v * adstP[jj];
                    } else {
                        v += bp ? bp[j] : 0.f;
                        if (mode != 0) v = softplusf(v);
                        if (mode == 2) v = fminf(fmaxf(v, 0.1f), 1000.f);
                        if (mode >= 2) o[(size_t)j * stride + row] = v;
                        else           o[(size_t)row * stride + j] = v;
                    }
                }
            }
            if (mode == 4) {
                int h = jbase / headC;       // warp tile lies in exactly one head
                atomicAdd(&sOut[row * 4 + h], ss);
                atomicAdd(&dOut[row * 4 + h], dd);
            }
        }
    }
}

// ================= fused per-node GAT v2: dedup exp via smem tiles =================
template <int C>
__global__ void gat_kernel(const int* __restrict__ csr, const int* __restrict__ off,
                           const float* __restrict__ s, const float* __restrict__ d,
                           const float* __restrict__ xw, const float* __restrict__ bias,
                           float* __restrict__ out) {
    constexpr int HC = 4 * C;
    constexpr int TILE = HC / 4;         // 64 (C=64) or 32 (C=32)
    const int v = blockIdx.x;
    const int tid = threadIdx.x;
    const int h = tid / C;
    const int c = tid - h * C;
    const int beg = off[v], end = off[v + 1];

    __shared__ float red[HC];
    __shared__ float mh[4], inv[4];
    __shared__ float wsh[TILE * 4];
    __shared__ int   ush[TILE];

    const float dv = d[v * 4 + h];

    // pass 1: per-head max of leaky(s[u]+d[v])
    float lmax = -INFINITY;
    for (int j = beg + c; j < end; j += C) {
        int u = csr[j];
        float e = s[u * 4 + h] + dv;
        e = e > 0.f ? e : 0.2f * e;
        lmax = fmaxf(lmax, e);
    }
    red[tid] = lmax;
    __syncthreads();
    if (tid < 4) {
        float m = -INFINITY;
        for (int i = 0; i < C; i++) m = fmaxf(m, red[tid * C + i]);
        mh[tid] = m;
    }
    __syncthreads();
    const float m = mh[h];

    // pass 2: per-head sum of exp(e - m)
    float lsum = 0.f;
    for (int j = beg + c; j < end; j += C) {
        int u = csr[j];
        float e = s[u * 4 + h] + dv;
        e = e > 0.f ? e : 0.2f * e;
        lsum += __expf(e - m);
    }
    red[tid] = lsum;
    __syncthreads();
    if (tid < 4) {
        float sm = 0.f;
        for (int i = 0; i < C; i++) sm += red[tid * C + i];
        inv[tid] = 1.f / (sm + 1e-16f);
    }
    __syncthreads();

    // pass 3: tiled — compute w once per (edge, head), then broadcast aggregate
    float acc = 0.f;
    const int je = tid >> 2;
    const int hh = tid & 3;
    for (int t0 = beg; t0 < end; t0 += TILE) {
        int mc = end - t0; if (mc > TILE) mc = TILE;
        if (je < mc) {
            int u = csr[t0 + je];
            if (hh == 0) ush[je] = u;
            float e = s[u * 4 + hh] + d[v * 4 + hh];
            e = e > 0.f ? e : 0.2f * e;
            wsh[je * 4 + hh] = __expf(e - mh[hh]) * inv[hh];
        }
        __syncthreads();
        for (int q = 0; q < mc; q++)
            acc = fmaf(wsh[q * 4 + h], xw[(size_t)ush[q] * HC + tid], acc);
        __syncthreads();
    }
    out[(size_t)v * HC + tid] = acc + bias[tid];
}

// ---------------- fused kl_fix + theta ----------------
__global__ void theta_kernel(const float* __restrict__ k, float* __restrict__ l,
                             const float* __restrict__ eps, float* __restrict__ th, int ZN) {
    int i = blockIdx.x * blockDim.x + threadIdx.x;
    if (i >= ZN) return;
    float kk = k[i];
    float invk = 1.f / kk;
    float ll = fmaxf(l[i], 2.2e-10f) * expf(-lgammaf(1.f + invk));
    l[i] = ll;
    float acc = 0.f;
#pragma unroll
    for (int s = 0; s < 10; s++) {
        float ep = eps[(size_t)s * ZN + i];
        float t = fmaxf(1.f - ep, 2.2e-10f);
        float nl = -__logf(t);
        acc += __powf(nl, invk);
    }
    float theta = ll * acc * 0.1f;
    th[i] = fminf(fmaxf(theta, 2.2e-10f), 1000.f);
}

// ---------------- host launch ----------------
template <typename T>
static float* symaddrf(T& sym) { void* p = nullptr; cudaGetSymbolAddress(&p, sym); return (float*)p; }
template <typename T>
static int* symaddri(T& sym) { void* p = nullptr; cudaGetSymbolAddress(&p, sym); return (int*)p; }

static cudaStream_t g_s2 = nullptr;
static cudaEvent_t g_evA, g_evCSR, g_evZ0, g_evT0;

extern "C" void kernel_launch(void* const* d_in, const int* in_sizes, int n_in,
                              void* d_out, int out_size) {
    if (!g_s2) {
        cudaStreamCreateWithFlags(&g_s2, cudaStreamNonBlocking);
        cudaEventCreateWithFlags(&g_evA,   cudaEventDisableTiming);
        cudaEventCreateWithFlags(&g_evCSR, cudaEventDisableTiming);
        cudaEventCreateWithFlags(&g_evZ0,  cudaEventDisableTiming);
        cudaEventCreateWithFlags(&g_evT0,  cudaEventDisableTiming);
    }

    const float* x     = (const float*)d_in[0];
    const int*   ei    = (const int*)  d_in[1];
    const float* gatW0 = (const float*)d_in[2];
    const float* asrc0 = (const float*)d_in[3];
    const float* adst0 = (const float*)d_in[4];
    const float* gatb0 = (const float*)d_in[5];
    const float* fcW0  = (const float*)d_in[6];
    const float* fcb0  = (const float*)d_in[7];
    const float* shW0  = (const float*)d_in[8];
    const float* shb0  = (const float*)d_in[9];
    const float* scW0  = (const float*)d_in[10];
    const float* scb0  = (const float*)d_in[11];
    const float* gatW1 = (const float*)d_in[12];
    const float* asrc1 = (const float*)d_in[13];
    const float* adst1 = (const float*)d_in[14];
    const float* gatb1 = (const float*)d_in[15];
    const float* fcW1  = (const float*)d_in[16];
    const float* fcb1  = (const float*)d_in[17];
    const float* shW1  = (const float*)d_in[18];
    const float* shb1  = (const float*)d_in[19];
    const float* scW1  = (const float*)d_in[20];
    const float* scb1  = (const float*)d_in[21];
    const float* eps0  = (const float*)d_in[22];
    const float* eps1  = (const float*)d_in[23];

    const int n = N_NODES;
    float* out = (float*)d_out;
    float* theta0 = out;
    float* theta1 = theta0 + (size_t)128 * n;
    float* k0     = theta1 + (size_t)64  * n;
    float* k1     = k0     + (size_t)128 * n;
    float* l0     = k1     + (size_t)64  * n;
    float* l1     = l0     + (size_t)128 * n;

    float* xw0 = symaddrf(g_xw0);
    float* h0  = symaddrf(g_h0);
    float* xw1 = symaddrf(g_xw1);
    float* h1  = symaddrf(g_h1);
    float* z0  = symaddrf(g_z0);
    float* z1  = symaddrf(g_z1);
    float* s0  = symaddrf(g_s0);
    float* d0  = symaddrf(g_d0);
    float* s1  = symaddrf(g_s1);
    float* d1  = symaddrf(g_d1);
    float* wf01 = symaddrf(g_wf01);
    float* wkl0 = symaddrf(g_wkl0);
    float* wkl1 = symaddrf(g_wkl1);
    int* cnt = symaddri(g_cnt);
    int* cur = symaddri(g_cur);
    int* off = symaddri(g_off);
    int* csr = symaddri(g_csr);

    const int EB = (ET + 255) / 256;
    const int GX = (n + 127) / 128;       // 157 row tiles

    // ===== d: init, then fork CSR build + concat to s2 =====
    init_kernel<<<(4 * n + 255) / 256, 256>>>(cnt, s0, d0, s1, d1);
    cudaEventRecord(g_evA, 0);
    cudaStreamWaitEvent(g_s2, g_evA, 0);

    // ---- s2: CSR build + weight concat (overlaps xw0 GEMM on d) ----
    hist_kernel<<<EB, 256, 0, g_s2>>>(ei, cnt);
    scan_kernel<<<1, 1024, 0, g_s2>>>(cnt, off, cur);
    scatter_kernel<<<EB, 256, 0, g_s2>>>(ei, off, cur, csr);
    concat_kernel<<<128, 256, 0, g_s2>>>(wf01, wkl0, wkl1, gatW1, fcW0, shW0, scW0, shW1, scW1);
    cudaEventRecord(g_evCSR, g_s2);

    // ---- d: xw0 GEMM (mode 4 -> xw0, s0, d0) at capture index 3 (profiled) ----
    gemm_mma_kernel<<<dim3(GX, 4), 256>>>(x, gatW0, n, 256, 1 << 30,
                                          xw0, nullptr, 4, 256,
                                          nullptr, nullptr, 0, 0,
                                          asrc0, adst0, s0, d0, 64);

    // ---- d: join CSR+concat, then layer-0 GAT + fused xw1/z0 GEMM ----
    cudaStreamWaitEvent(0, g_evCSR, 0);
    gat_kernel<64><<<n, 256>>>(csr, off, s0, d0, xw0, gatb0, h0);
    gemm_mma_kernel<<<dim3(GX, 4), 256>>>(h0, wf01, n, 256, 128,
                                          xw1, nullptr, 4, 128,
                                          z0, fcb0, 1, 128,
                                          asrc1, adst1, s1, d1, 32);
    cudaEventRecord(g_evZ0, 0);

    // ---- s2: layer-0 head chain (kl0 -> theta0), overlaps with layer-1 chain on d ----
    cudaStreamWaitEvent(g_s2, g_evZ0, 0);
    gemm_mma_kernel<<<dim3(GX, 4), 256, 0, g_s2>>>(z0, wkl0, n, 128, 128,
                                                   k0, shb0, 2, n,
                                                   l0, scb0, 3, n,
                                                   nullptr, nullptr, nullptr, nullptr, 1);
    theta_kernel<<<(128 * n + 255) / 256, 256, 0, g_s2>>>(k0, l0, eps0, theta0, 128 * n);
    cudaEventRecord(g_evT0, g_s2);

    // ---- d: layer-1 chain (gat1 -> z1 -> kl1 -> theta1) ----
    gat_kernel<32><<<n, 128>>>(csr, off, s1, d1, xw1, gatb1, h1);
    gemm_mma_kernel<<<dim3(GX, 1), 256>>>(h1, fcW1, n, 128, 1 << 30,
                                          z1, fcb1, 1, 64,
                                          nullptr, nullptr, 0, 0,
                                          nullptr, nullptr, nullptr, nullptr, 1);
    gemm_mma_kernel<<<dim3(GX, 2), 256>>>(z1, wkl1, n, 64, 64,
                                          k1, shb1, 2, n,
                                          l1, scb1, 3, n,
                                          nullptr, nullptr, nullptr, nullptr, 1);
    theta_kernel<<<(64 * n + 255) / 256, 256>>>(k1, l1, eps1, theta1, 64 * n);

    // ---- join s2 back into d before return ----
    cudaStreamWaitEvent(0, g_evT0, 0);
}